// round 1
// baseline (speedup 1.0000x reference)
#include <cuda_runtime.h>
#include <cstdint>

#define Bn   64
#define Nn   207
#define Tn   48
#define Fin  6
#define Hd   64
#define NSEQ (Bn * Nn)        // 13248

// ---------------- scratch: GCN output, LSTM input [seq][t][Hd] ----------------
__device__ float g_h2[(size_t)NSEQ * Tn * Hd];   // 162.8 MB, static device global

// ---------------- helpers ----------------
__device__ __forceinline__ float sigm(float x) {
    // 1/(1+e^-x): EX2 + RCP, safe at both tails
    return __fdividef(1.0f, 1.0f + __expf(-x));
}
__device__ __forceinline__ float tanh_fast(float x) {
    float ax = fabsf(x);
    float e  = __expf(-2.0f * ax);            // in (0,1], no overflow
    float r  = __fdividef(1.0f - e, 1.0f + e);
    return copysignf(r, x);
}

#define PACK2(d, s)  asm("mov.b64 %0, {%1, %1};" : "=l"(d) : "f"(s))
#define UNPK2(a, b, v) asm("mov.b64 {%0, %1}, %2;" : "=f"(a), "=f"(b) : "l"(v))
#define FMA2(acc, a, b) asm("fma.rn.f32x2 %0, %1, %2, %0;" : "+l"(acc) : "l"(a), "l"(b))

// =====================================================================
// Kernel 1: fused 2-layer GCN.  grid (Tn, Bn), 256 threads.
// A_hat[m][n] = (1 + (m==n)) / 208  ->  out = (colsum + self)/208
// =====================================================================
__global__ void __launch_bounds__(256) gcn_kernel(
    const float* __restrict__ x,  const float* __restrict__ W1,
    const float* __restrict__ b1, const float* __restrict__ W2,
    const float* __restrict__ b2)
{
    extern __shared__ float sm[];
    float* W1s  = sm;             // 384
    float* b1s  = W1s + 384;      // 64
    float* W2s  = b1s + 64;       // 4096
    float* b2s  = W2s + 4096;     // 64
    float* xs   = b2s + 64;       // 207*6 = 1242
    float* buf  = xs + 1242;      // 207*64 = 13248 (z1 -> h1 in place)
    float* S1   = buf + 13248;    // 64
    float* SH   = S1 + 64;        // 64
    float* S2   = SH + 64;        // 64
    float* part = S2 + 64;        // 256

    const int t = blockIdx.x, b = blockIdx.y;
    const int tid = threadIdx.x;
    const float inv = 1.0f / 208.0f;

    for (int i = tid; i < 384;  i += 256) W1s[i] = W1[i];
    for (int i = tid; i < 4096; i += 256) W2s[i] = W2[i];
    if (tid < 64) { b1s[tid] = b1[tid]; b2s[tid] = b2[tid]; }
    for (int i = tid; i < Nn * Fin; i += 256) {
        int n = i / 6, f = i - n * 6;
        xs[i] = x[((size_t)(b * Nn + n) * Tn + t) * Fin + f];
    }
    __syncthreads();

    // z1 = x @ W1
    for (int i = tid; i < Nn * Hd; i += 256) {
        int n = i >> 6, j = i & 63;
        const float* xr = xs + n * 6;
        float a = xr[0] * W1s[j]       + xr[1] * W1s[64 + j];
        a      += xr[2] * W1s[128 + j] + xr[3] * W1s[192 + j];
        a      += xr[4] * W1s[256 + j] + xr[5] * W1s[320 + j];
        buf[i] = a;
    }
    __syncthreads();

    // S1[j] = sum_n z1[n][j]
    {
        int j = tid & 63, qr = tid >> 6;
        float s = 0.f;
        for (int n = qr; n < Nn; n += 4) s += buf[n * 64 + j];
        part[qr * 64 + j] = s;
    }
    __syncthreads();
    if (tid < 64) S1[tid] = part[tid] + part[64 + tid] + part[128 + tid] + part[192 + tid];
    __syncthreads();

    // h1 = relu((S1 + z1)/208 + b1)  (in place)
    for (int i = tid; i < Nn * Hd; i += 256) {
        int j = i & 63;
        buf[i] = fmaxf((S1[j] + buf[i]) * inv + b1s[j], 0.f);
    }
    __syncthreads();

    // SH[j] = sum_n h1[n][j]
    {
        int j = tid & 63, qr = tid >> 6;
        float s = 0.f;
        for (int n = qr; n < Nn; n += 4) s += buf[n * 64 + j];
        part[qr * 64 + j] = s;
    }
    __syncthreads();
    if (tid < 64) SH[tid] = part[tid] + part[64 + tid] + part[128 + tid] + part[192 + tid];
    __syncthreads();
    // S2 = SH @ W2  (colsum of z2, computed cheaply)
    if (tid < 64) {
        float s = 0.f;
        #pragma unroll 8
        for (int k = 0; k < 64; ++k) s += SH[k] * W2s[k * 64 + tid];
        S2[tid] = s;
    }
    __syncthreads();

    // z2 = h1 @ W2 ; h2 = relu((S2 + z2)/208 + b2) -> global
    for (int p = tid; p < Nn * 32; p += 256) {
        int n = p >> 5, j2 = p & 31;
        unsigned long long acc = 0ull;
        const float* hr = buf + n * 64;
        const float* wp = W2s + j2 * 2;
        #pragma unroll 8
        for (int k = 0; k < 64; ++k) {
            unsigned long long wv = *(const unsigned long long*)(wp + k * 64);
            unsigned long long hp;
            PACK2(hp, hr[k]);
            FMA2(acc, wv, hp);
        }
        float z0, z1v;
        UNPK2(z0, z1v, acc);
        int j = j2 * 2;
        float2 o;
        o.x = fmaxf((S2[j]     + z0 ) * inv + b2s[j],     0.f);
        o.y = fmaxf((S2[j + 1] + z1v) * inv + b2s[j + 1], 0.f);
        *(float2*)&g_h2[((size_t)(b * Nn + n) * Tn + t) * Hd + j] = o;
    }
}

// =====================================================================
// Kernel 2: persistent warp-autonomous LSTM + final FC.
// 138 blocks x 384 threads; warp owns 8 sequences; lane owns hidden
// units {2*lane, 2*lane+1} across all 4 gate groups; accumulators packed
// f32x2 over sequence pairs.
// =====================================================================
#define WARPS 12
#define BLKT  (WARPS * 32)      // 384
#define SPW   8                 // seqs per warp
#define SPB   (WARPS * SPW)     // 96
#define NBLK  138               // 138*96 == 13248 exactly
#define XS    10                // padded stride of [j][s] tiles

__global__ void __launch_bounds__(BLKT, 1) lstm_kernel(
    const float* __restrict__ Wih, const float* __restrict__ Whh,
    const float* __restrict__ bih, const float* __restrict__ bhh,
    const float* __restrict__ Wfc, const float* __restrict__ bfc,
    float* __restrict__ out)
{
    extern __shared__ float sm[];
    float* WihT  = sm;                  // [k][g] 64*256
    float* WhhT  = WihT + 16384;        // [k][g] 64*256
    float* bias  = WhhT + 16384;        // 256 (b_ih + b_hh)
    float* wfcs  = bias + 256;          // 64
    float* xbase = wfcs + 64;           // WARPS * 64*XS
    float* hbase = xbase + WARPS * Hd * XS;

    const int tid = threadIdx.x;
    for (int i = tid; i < 16384; i += BLKT) {
        int g = i >> 6, k = i & 63;
        WihT[k * 256 + g] = Wih[i];
        WhhT[k * 256 + g] = Whh[i];
    }
    for (int i = tid; i < 256; i += BLKT) bias[i] = bih[i] + bhh[i];
    if (tid < 64) wfcs[tid] = Wfc[tid];

    const int w = tid >> 5, lane = tid & 31;
    float* xs = xbase + w * (Hd * XS);
    float* hs = hbase + w * (Hd * XS);
    const int seq0 = blockIdx.x * SPB + w * SPW;
    const int j0 = lane * 2;

    for (int i = lane; i < Hd * XS; i += 32) hs[i] = 0.f;
    __syncthreads();

    float br[8];
    #pragma unroll
    for (int ty = 0; ty < 4; ++ty) {
        br[ty * 2 + 0] = bias[ty * 64 + j0 + 0];
        br[ty * 2 + 1] = bias[ty * 64 + j0 + 1];
    }

    float c[2][8];
    #pragma unroll
    for (int q = 0; q < 2; ++q)
        #pragma unroll
        for (int s = 0; s < 8; ++s) c[q][s] = 0.f;

    for (int t = 0; t < Tn; ++t) {
        // stage x_t transposed [j][s]
        for (int i = lane; i < SPW * Hd; i += 32) {
            int s = i >> 6, j = i & 63;
            int seq = seq0 + s;
            float v = 0.f;
            if (seq < NSEQ) v = g_h2[((size_t)seq * Tn + t) * Hd + j];
            xs[j * XS + s] = v;
        }
        __syncwarp();

        unsigned long long acc[8][4];
        #pragma unroll
        for (int g = 0; g < 8; ++g)
            #pragma unroll
            for (int sp = 0; sp < 4; ++sp) acc[g][sp] = 0ull;

        #pragma unroll 8
        for (int k = 0; k < 64; ++k) {
            const float* xk = xs + k * XS;
            const float* hk = hs + k * XS;
            unsigned long long x2[4], h2[4];
            #pragma unroll
            for (int sp = 0; sp < 4; ++sp) {
                x2[sp] = *(const unsigned long long*)(xk + 2 * sp);
                h2[sp] = *(const unsigned long long*)(hk + 2 * sp);
            }
            const float* wi = WihT + k * 256 + j0;
            const float* wh = WhhT + k * 256 + j0;
            #pragma unroll
            for (int ty = 0; ty < 4; ++ty) {
                float2 wiv = *(const float2*)(wi + ty * 64);
                float2 whv = *(const float2*)(wh + ty * 64);
                unsigned long long wi0, wi1, wh0, wh1;
                PACK2(wi0, wiv.x); PACK2(wi1, wiv.y);
                PACK2(wh0, whv.x); PACK2(wh1, whv.y);
                #pragma unroll
                for (int sp = 0; sp < 4; ++sp) {
                    FMA2(acc[ty * 2 + 0][sp], wi0, x2[sp]);
                    FMA2(acc[ty * 2 + 0][sp], wh0, h2[sp]);
                    FMA2(acc[ty * 2 + 1][sp], wi1, x2[sp]);
                    FMA2(acc[ty * 2 + 1][sp], wh1, h2[sp]);
                }
            }
        }
        __syncwarp();   // all lanes done reading hs before overwrite

        #pragma unroll
        for (int q = 0; q < 2; ++q) {
            #pragma unroll
            for (int sp = 0; sp < 4; ++sp) {
                float gi0, gi1, gf0, gf1, gg0, gg1, go0, go1;
                UNPK2(gi0, gi1, acc[0 + q][sp]);
                UNPK2(gf0, gf1, acc[2 + q][sp]);
                UNPK2(gg0, gg1, acc[4 + q][sp]);
                UNPK2(go0, go1, acc[6 + q][sp]);
                {
                    int s = 2 * sp;
                    float ii = sigm(gi0 + br[q]);
                    float ff = sigm(gf0 + br[2 + q]);
                    float gt = tanh_fast(gg0 + br[4 + q]);
                    float oo = sigm(go0 + br[6 + q]);
                    float cn = ff * c[q][s] + ii * gt;
                    c[q][s] = cn;
                    hs[(j0 + q) * XS + s] = oo * tanh_fast(cn);
                }
                {
                    int s = 2 * sp + 1;
                    float ii = sigm(gi1 + br[q]);
                    float ff = sigm(gf1 + br[2 + q]);
                    float gt = tanh_fast(gg1 + br[4 + q]);
                    float oo = sigm(go1 + br[6 + q]);
                    float cn = ff * c[q][s] + ii * gt;
                    c[q][s] = cn;
                    hs[(j0 + q) * XS + s] = oo * tanh_fast(cn);
                }
            }
        }
        // next iteration's post-x-load __syncwarp orders these writes
        // before the next k-loop reads; no extra barrier needed here.
    }
    __syncwarp();

    // final FC: out[seq] = h_T . W_fc + b_fc
    if (lane < SPW) {
        int seq = seq0 + lane;
        if (seq < NSEQ) {
            float a = bfc[0];
            #pragma unroll 8
            for (int j = 0; j < 64; ++j) a += hs[j * XS + lane] * wfcs[j];
            out[seq] = a;
        }
    }
}

// =====================================================================
extern "C" void kernel_launch(void* const* d_in, const int* in_sizes, int n_in,
                              void* d_out, int out_size)
{
    const float* x   = (const float*)d_in[0];
    // d_in[1], d_in[2] = N1, N2: structurally irrelevant (sigmoid > 0 everywhere)
    const float* W1  = (const float*)d_in[3];
    const float* b1  = (const float*)d_in[4];
    const float* W2  = (const float*)d_in[5];
    const float* b2  = (const float*)d_in[6];
    const float* Wih = (const float*)d_in[7];
    const float* Whh = (const float*)d_in[8];
    const float* bih = (const float*)d_in[9];
    const float* bhh = (const float*)d_in[10];
    const float* Wfc = (const float*)d_in[11];
    const float* bfc = (const float*)d_in[12];
    float* out = (float*)d_out;

    const size_t gcn_smem  = 19546u * 4u;   // 78,184 B
    const size_t lstm_smem = (size_t)(33088 + 2 * WARPS * Hd * XS) * 4u; // 193,792 B

    cudaFuncSetAttribute(gcn_kernel,  cudaFuncAttributeMaxDynamicSharedMemorySize, (int)gcn_smem);
    cudaFuncSetAttribute(lstm_kernel, cudaFuncAttributeMaxDynamicSharedMemorySize, (int)lstm_smem);

    gcn_kernel<<<dim3(Tn, Bn), 256, gcn_smem>>>(x, W1, b1, W2, b2);
    lstm_kernel<<<NBLK, BLKT, lstm_smem>>>(Wih, Whh, bih, bhh, Wfc, bfc, out);
}

// round 2
// speedup vs baseline: 1.3744x; 1.3744x over previous
#include <cuda_runtime.h>
#include <cstdint>

#define Bn   64
#define Nn   207
#define Tn   48
#define Fin  6
#define Hd   64
#define NSEQ (Bn * Nn)        // 13248

// scratch: GCN output / LSTM input, [seq][t][Hd]
__device__ float g_h2[(size_t)NSEQ * Tn * Hd];   // 162.8 MB

#define PACK2(d, s)    asm("mov.b64 %0, {%1, %1};" : "=l"(d) : "f"(s))
#define UNPK2(a, b, v) asm("mov.b64 {%0, %1}, %2;" : "=f"(a), "=f"(b) : "l"(v))
#define FMA2(acc, a, b) asm("fma.rn.f32x2 %0, %1, %2, %0;" : "+l"(acc) : "l"(a), "l"(b))

__device__ __forceinline__ float tanhm(float x) {
    float r; asm("tanh.approx.f32 %0, %1;" : "=f"(r) : "f"(x)); return r;
}
// sigmoid(x + b) with bh = 0.5*b precomputed
__device__ __forceinline__ float sigm2(float x, float bh) {
    return fmaf(tanhm(fmaf(x, 0.5f, bh)), 0.5f, 0.5f);
}

// bank-swizzled slot base for 64 rows x 8 floats (optimal 4-phase stores,
// uniform-address broadcast reads). Injective, 16B-aligned, range [0,512).
__device__ __forceinline__ int PJ(int j) {
    return ((j & 3) << 6) + (((j >> 2) & 7) << 3) + ((j >> 5) << 8);
}

// =====================================================================
// Kernel 1: fused 2-layer GCN.  grid (Tn, Bn), 256 threads.
// A_hat[m][n] = (1 + (m==n)) / 208
// =====================================================================
#define NS 216   // padded row stride of bufT (16B-aligned, odd/4 for banks)

__global__ void __launch_bounds__(256, 2) gcn_kernel(
    const float* __restrict__ x,  const float* __restrict__ W1,
    const float* __restrict__ b1, const float* __restrict__ W2,
    const float* __restrict__ b2)
{
    extern __shared__ float sm[];
    float* W1s  = sm;               // 384
    float* W2s  = W1s + 384;        // 4096
    float* b1s  = W2s + 4096;       // 64
    float* b2s  = b1s + 64;         // 64
    float* S1   = b2s + 64;         // 64
    float* SH   = S1 + 64;          // 64
    float* S2   = SH + 64;          // 64
    float* xsum = S2 + 64;          // 8
    float* part = xsum + 8;         // 256
    float* xs   = part + 256;       // 1248 (uses 1242)
    float* bufT = xs + 1248;        // 64 * NS  (h1 transposed [k][n])

    const int t = blockIdx.x, b = blockIdx.y;
    const int tid = threadIdx.x;
    const float inv = 1.0f / 208.0f;

    for (int i = tid; i < 384;  i += 256) W1s[i] = W1[i];
    for (int i = tid; i < 4096; i += 256) W2s[i] = W2[i];
    if (tid < 64) { b1s[tid] = b1[tid]; b2s[tid] = b2[tid]; }
    {
        const float* xb = x + (size_t)b * (Nn * Tn * Fin) + t * Fin;
        for (int i = tid; i < Nn * Fin; i += 256) {
            int n = i / 6, f = i - n * 6;
            xs[i] = xb[n * (Tn * Fin) + f];
        }
    }
    __syncthreads();

    // xsum[f] = sum_n x[n][f]  (48 threads: 8 chunks x 6 feats)
    if (tid < 48) {
        int f = tid % 6, q = tid / 6;
        float s = 0.f;
        for (int n = q; n < Nn; n += 8) s += xs[n * 6 + f];
        part[tid] = s;
    }
    __syncthreads();
    if (tid < 6) {
        float s = 0.f;
        #pragma unroll
        for (int q = 0; q < 8; ++q) s += part[q * 6 + tid];
        xsum[tid] = s;
    }
    __syncthreads();
    // S1 = xsum @ W1  (colsum of z1, pre-relu shortcut)
    if (tid < 64) {
        float s = 0.f;
        #pragma unroll
        for (int f = 0; f < 6; ++f) s += xsum[f] * W1s[f * 64 + tid];
        S1[tid] = s;
    }
    __syncthreads();

    // h1 = relu((z1 + S1)/208 + b1), stored transposed bufT[j][n]
    {
        int j = tid >> 2, q = tid & 3;
        float w0 = W1s[j], w1 = W1s[64 + j], w2 = W1s[128 + j];
        float w3 = W1s[192 + j], w4 = W1s[256 + j], w5 = W1s[320 + j];
        float cj = fmaf(S1[j], inv, b1s[j]);
        float* row = bufT + j * NS;
        for (int n = q; n < Nn; n += 4) {
            const float* xr = xs + n * 6;
            float v = xr[0] * w0 + xr[1] * w1 + xr[2] * w2
                    + xr[3] * w3 + xr[4] * w4 + xr[5] * w5;
            row[n] = fmaxf(fmaf(v, inv, cj), 0.f);
        }
    }
    __syncthreads();

    // SH[j] = sum_n h1[j][n]
    {
        int j = tid >> 2, q = tid & 3;
        const float* row = bufT + j * NS;
        float s = 0.f;
        for (int n = q; n < Nn; n += 4) s += row[n];
        part[q * 64 + j] = s;
    }
    __syncthreads();
    if (tid < 64) SH[tid] = part[tid] + part[64 + tid] + part[128 + tid] + part[192 + tid];
    __syncthreads();
    // S2 = SH @ W2  (colsum of z2)
    if (tid < 64) {
        float s = 0.f;
        #pragma unroll 8
        for (int k = 0; k < 64; ++k) s += SH[k] * W2s[k * 64 + tid];
        S2[tid] = s;
    }
    __syncthreads();

    // z2 = h1 @ W2 ; h2 = relu((z2 + S2)/208 + b2) -> global
    {
        const int w = tid >> 5, lane = tid & 31;
        const int j = 2 * lane;
        const float a0 = fmaf(S2[j],     inv, b2s[j]);
        const float a1 = fmaf(S2[j + 1], inv, b2s[j + 1]);
        for (int tt = w; tt < 26; tt += 8) {
            const int n0 = tt * 8;
            const int nv = (n0 + 8 <= Nn) ? 8 : (Nn - n0);
            unsigned long long acc[8];
            #pragma unroll
            for (int r = 0; r < 8; ++r) acc[r] = 0ull;
            const float* hb = bufT + n0;
            #pragma unroll 16
            for (int k = 0; k < 64; ++k) {
                float4 hA = *(const float4*)(hb + k * NS);
                float4 hB = *(const float4*)(hb + k * NS + 4);
                unsigned long long wv = *(const unsigned long long*)(W2s + k * 64 + j);
                unsigned long long p;
                PACK2(p, hA.x); FMA2(acc[0], wv, p);
                PACK2(p, hA.y); FMA2(acc[1], wv, p);
                PACK2(p, hA.z); FMA2(acc[2], wv, p);
                PACK2(p, hA.w); FMA2(acc[3], wv, p);
                PACK2(p, hB.x); FMA2(acc[4], wv, p);
                PACK2(p, hB.y); FMA2(acc[5], wv, p);
                PACK2(p, hB.z); FMA2(acc[6], wv, p);
                PACK2(p, hB.w); FMA2(acc[7], wv, p);
            }
            #pragma unroll
            for (int r = 0; r < 8; ++r) {
                if (r < nv) {
                    float z0, z1; UNPK2(z0, z1, acc[r]);
                    float2 o;
                    o.x = fmaxf(fmaf(z0, inv, a0), 0.f);
                    o.y = fmaxf(fmaf(z1, inv, a1), 0.f);
                    *(float2*)&g_h2[((size_t)(b * Nn + n0 + r) * Tn + t) * Hd + j] = o;
                }
            }
        }
    }
}

// =====================================================================
// Kernel 2: persistent warp-autonomous LSTM + final FC.
// 138 blocks x 384 threads; warp owns 8 seqs; lane owns units {l, l+32}.
// =====================================================================
#define WARPS 12
#define BLKT  (WARPS * 32)
#define SPW   8
#define SPB   (WARPS * SPW)     // 96
#define NBLK  138               // 138*96 == 13248

__global__ void __launch_bounds__(BLKT, 1) lstm_kernel(
    const float* __restrict__ Wih, const float* __restrict__ Whh,
    const float* __restrict__ bih, const float* __restrict__ bhh,
    const float* __restrict__ Wfc, const float* __restrict__ bfc,
    float* __restrict__ out)
{
    extern __shared__ float sm[];
    float* WihP  = sm;                  // [k][uu][j][g]  64*256
    float* WhhP  = WihP + 16384;
    float* bias  = WhhP + 16384;        // 256
    float* wfcs  = bias + 256;          // 64
    float* stage = wfcs + 64;           // WARPS * 1024 (xs 512 | hs 512)

    const int tid = threadIdx.x;
    for (int i = tid; i < 16384; i += BLKT) {
        int k = i >> 8, r = i & 255;
        int uu = r >> 7, j = (r >> 2) & 31, g = r & 3;
        int row = g * 64 + uu * 32 + j;
        WihP[i] = Wih[row * 64 + k];
        WhhP[i] = Whh[row * 64 + k];
    }
    for (int i = tid; i < 256; i += BLKT) bias[i] = bih[i] + bhh[i];
    if (tid < 64) wfcs[tid] = Wfc[tid];

    const int w = tid >> 5, lane = tid & 31;
    float* xs = stage + w * 1024;
    float* hs = xs + 512;
    const int seq0 = blockIdx.x * SPB + w * SPW;

    for (int i = lane; i < 512; i += 32) hs[i] = 0.f;
    __syncthreads();

    float brh[2][4];
    #pragma unroll
    for (int uu = 0; uu < 2; ++uu)
        #pragma unroll
        for (int g = 0; g < 4; ++g) {
            float bb = bias[g * 64 + uu * 32 + lane];
            brh[uu][g] = (g == 2) ? bb : 0.5f * bb;
        }

    float c[2][8];
    #pragma unroll
    for (int uu = 0; uu < 2; ++uu)
        #pragma unroll
        for (int s = 0; s < 8; ++s) c[uu][s] = 0.f;

    const int pj0 = PJ(lane), pj1 = PJ(lane + 32);

    for (int t = 0; t < Tn; ++t) {
        // stage x_t: lane gathers column j over 8 seqs, stores swizzled
        #pragma unroll
        for (int uu = 0; uu < 2; ++uu) {
            int j = uu * 32 + lane;
            const float* gp = g_h2 + ((size_t)seq0 * Tn + t) * Hd + j;
            float4 v0, v1;
            v0.x = gp[0 * 3072]; v0.y = gp[1 * 3072];
            v0.z = gp[2 * 3072]; v0.w = gp[3 * 3072];
            v1.x = gp[4 * 3072]; v1.y = gp[5 * 3072];
            v1.z = gp[6 * 3072]; v1.w = gp[7 * 3072];
            int pj = uu ? pj1 : pj0;
            *(float4*)(xs + pj)     = v0;
            *(float4*)(xs + pj + 4) = v1;
        }
        __syncwarp();

        unsigned long long acc[2][4][4];
        #pragma unroll
        for (int uu = 0; uu < 2; ++uu)
            #pragma unroll
            for (int g = 0; g < 4; ++g)
                #pragma unroll
                for (int sp = 0; sp < 4; ++sp) acc[uu][g][sp] = 0ull;

        #pragma unroll 8
        for (int k = 0; k < 64; ++k) {
            const int pk = PJ(k);
            ulonglong2 xA = *(const ulonglong2*)(xs + pk);
            ulonglong2 xB = *(const ulonglong2*)(xs + pk + 4);
            ulonglong2 hA = *(const ulonglong2*)(hs + pk);
            ulonglong2 hB = *(const ulonglong2*)(hs + pk + 4);
            const float4 wiA = *(const float4*)(WihP + (k << 8) + (lane << 2));
            const float4 wiB = *(const float4*)(WihP + (k << 8) + 128 + (lane << 2));
            const float4 whA = *(const float4*)(WhhP + (k << 8) + (lane << 2));
            const float4 whB = *(const float4*)(WhhP + (k << 8) + 128 + (lane << 2));

            unsigned long long p;
            #define DO_GATE(uu, g, WI, WH) \
                PACK2(p, WI); \
                FMA2(acc[uu][g][0], p, xA.x); FMA2(acc[uu][g][1], p, xA.y); \
                FMA2(acc[uu][g][2], p, xB.x); FMA2(acc[uu][g][3], p, xB.y); \
                PACK2(p, WH); \
                FMA2(acc[uu][g][0], p, hA.x); FMA2(acc[uu][g][1], p, hA.y); \
                FMA2(acc[uu][g][2], p, hB.x); FMA2(acc[uu][g][3], p, hB.y);

            DO_GATE(0, 0, wiA.x, whA.x)
            DO_GATE(0, 1, wiA.y, whA.y)
            DO_GATE(0, 2, wiA.z, whA.z)
            DO_GATE(0, 3, wiA.w, whA.w)
            DO_GATE(1, 0, wiB.x, whB.x)
            DO_GATE(1, 1, wiB.y, whB.y)
            DO_GATE(1, 2, wiB.z, whB.z)
            DO_GATE(1, 3, wiB.w, whB.w)
            #undef DO_GATE
        }
        __syncwarp();

        #pragma unroll
        for (int uu = 0; uu < 2; ++uu) {
            float hv[8];
            #pragma unroll
            for (int sp = 0; sp < 4; ++sp) {
                float i0, i1, f0, f1, g0, g1, o0, o1;
                UNPK2(i0, i1, acc[uu][0][sp]);
                UNPK2(f0, f1, acc[uu][1][sp]);
                UNPK2(g0, g1, acc[uu][2][sp]);
                UNPK2(o0, o1, acc[uu][3][sp]);
                {
                    int s = 2 * sp;
                    float ig = sigm2(i0, brh[uu][0]);
                    float fg = sigm2(f0, brh[uu][1]);
                    float gg = tanhm(g0 + brh[uu][2]);
                    float og = sigm2(o0, brh[uu][3]);
                    float cn = fmaf(fg, c[uu][s], ig * gg);
                    c[uu][s] = cn;
                    hv[s] = og * tanhm(cn);
                }
                {
                    int s = 2 * sp + 1;
                    float ig = sigm2(i1, brh[uu][0]);
                    float fg = sigm2(f1, brh[uu][1]);
                    float gg = tanhm(g1 + brh[uu][2]);
                    float og = sigm2(o1, brh[uu][3]);
                    float cn = fmaf(fg, c[uu][s], ig * gg);
                    c[uu][s] = cn;
                    hv[s] = og * tanhm(cn);
                }
            }
            int pj = uu ? pj1 : pj0;
            *(float4*)(hs + pj)     = make_float4(hv[0], hv[1], hv[2], hv[3]);
            *(float4*)(hs + pj + 4) = make_float4(hv[4], hv[5], hv[6], hv[7]);
        }
    }
    __syncwarp();

    if (lane < SPW) {
        int seq = seq0 + lane;
        float a = bfc[0];
        #pragma unroll 8
        for (int j = 0; j < 64; ++j) a += hs[PJ(j) + lane] * wfcs[j];
        out[seq] = a;
    }
}

// =====================================================================
extern "C" void kernel_launch(void* const* d_in, const int* in_sizes, int n_in,
                              void* d_out, int out_size)
{
    const float* x   = (const float*)d_in[0];
    // d_in[1], d_in[2] = N1, N2: structurally irrelevant (sigmoid > 0 everywhere)
    const float* W1  = (const float*)d_in[3];
    const float* b1  = (const float*)d_in[4];
    const float* W2  = (const float*)d_in[5];
    const float* b2  = (const float*)d_in[6];
    const float* Wih = (const float*)d_in[7];
    const float* Whh = (const float*)d_in[8];
    const float* bih = (const float*)d_in[9];
    const float* bhh = (const float*)d_in[10];
    const float* Wfc = (const float*)d_in[11];
    const float* bfc = (const float*)d_in[12];
    float* out = (float*)d_out;

    const size_t gcn_smem  = (size_t)(384 + 4096 + 64 * 5 + 8 + 256 + 1248 + 64 * NS) * 4u;
    const size_t lstm_smem = (size_t)(16384 * 2 + 256 + 64 + WARPS * 1024) * 4u;

    cudaFuncSetAttribute(gcn_kernel,  cudaFuncAttributeMaxDynamicSharedMemorySize, (int)gcn_smem);
    cudaFuncSetAttribute(lstm_kernel, cudaFuncAttributeMaxDynamicSharedMemorySize, (int)lstm_smem);

    gcn_kernel<<<dim3(Tn, Bn), 256, gcn_smem>>>(x, W1, b1, W2, b2);
    lstm_kernel<<<NBLK, BLKT, lstm_smem>>>(Wih, Whh, bih, bhh, Wfc, bfc, out);
}